// round 15
// baseline (speedup 1.0000x reference)
#include <cuda_runtime.h>
#include <cstdint>
#include <cstddef>

// Problem constants
#define B_    4
#define C_    64
#define H_    256
#define W_    256
#define HW_   (H_*W_)          // 65536
#define WS_   8
#define OWS_  12
#define PAD_  2
#define NO_   144
#define NH_   4
#define HEAD_ 16
#define SCALE_ 0.25f
#define NW_   1024
#define LOG2E_ 1.4426950408889634f

typedef unsigned long long ull;

// ---- misc helpers ----------------------------------------------------------
__device__ __forceinline__ float ex2f(float x) {
    float r; asm("ex2.approx.f32 %0, %1;" : "=f"(r) : "f"(x)); return r;
}
__device__ __forceinline__ uint32_t tf32u(float a) {   // rna round to tf32 bits
    uint32_t u; asm("cvt.rna.tf32.f32 %0, %1;" : "=r"(u) : "f"(a));
    return u;
}
// rn-rounded bf16 pair: low half = lo, high half = hi
__device__ __forceinline__ uint32_t bf16x2(float lo, float hi) {
    uint32_t r; asm("cvt.rn.satfinite.bf16x2.f32 %0, %1, %2;"
                    : "=r"(r) : "f"(hi), "f"(lo));
    return r;
}
// truncation-pack: {hi16(b), hi16(a)} -> bf16 pair (low half = a), EXACT split
__device__ __forceinline__ uint32_t hi_pack(float a, float b) {
    uint32_t r; asm("prmt.b32 %0, %1, %2, 0x7632;"
                    : "=r"(r) : "r"(__float_as_uint(a)), "r"(__float_as_uint(b)));
    return r;
}
__device__ __forceinline__ float bft(float x) {   // truncate to bf16 value
    return __uint_as_float(__float_as_uint(x) & 0xFFFF0000u);
}

// m16n8k8 tf32 mma (sm_80+ PTX)
__device__ __forceinline__ void mma_tf32(float* d,
                                         uint32_t a0, uint32_t a1,
                                         uint32_t a2, uint32_t a3,
                                         uint32_t b0, uint32_t b1)
{
    asm volatile(
        "mma.sync.aligned.m16n8k8.row.col.f32.tf32.tf32.f32 "
        "{%0,%1,%2,%3}, {%4,%5,%6,%7}, {%8,%9}, {%0,%1,%2,%3};"
        : "+f"(d[0]), "+f"(d[1]), "+f"(d[2]), "+f"(d[3])
        : "r"(a0), "r"(a1), "r"(a2), "r"(a3), "r"(b0), "r"(b1));
}

// m16n8k16 bf16 mma (sm_80+ PTX)
__device__ __forceinline__ void mma_bf16(float* d,
                                         uint32_t a0, uint32_t a1,
                                         uint32_t a2, uint32_t a3,
                                         uint32_t b0, uint32_t b1)
{
    asm volatile(
        "mma.sync.aligned.m16n8k16.row.col.f32.bf16.bf16.f32 "
        "{%0,%1,%2,%3}, {%4,%5,%6,%7}, {%8,%9}, {%0,%1,%2,%3};"
        : "+f"(d[0]), "+f"(d[1]), "+f"(d[2]), "+f"(d[3])
        : "r"(a0), "r"(a1), "r"(a2), "r"(a3), "r"(b0), "r"(b1));
}

// Scratch. q/v position-major [b][pos][c]; k CHANNEL-major [b][c][pos].
__device__ float g_q [(size_t)B_*HW_*C_];
__device__ float g_k [(size_t)B_*HW_*C_];
__device__ float g_v [(size_t)B_*HW_*C_];

// ---------------------------------------------------------------------------
// QKV GEMM via mma.sync tf32, single pass (R14, proven).
// Block 64x128x64, 256 thr, warps 4(M) x 2(N), 4 CTAs/SM.
// ---------------------------------------------------------------------------
#define AHI_OFF  0
#define XS_OFF   (64*68)
#define GEMM_SMEM ((64*68 + 64*136) * 4)   // 52224 bytes

struct MmaOut { float d[8][4]; };

__device__ __forceinline__ void gemm_mma_core(const uint32_t* sm,
                                              int wid, int lane, MmaOut& O)
{
    const int m0  = (wid & 3) * 16;
    const int nw0 = (wid >> 2) * 64;
    const int lq  = lane >> 2;
    const int lr  = lane & 3;

    int aoff = AHI_OFF + (m0 + lq) * 68 + lr;
    int boff = XS_OFF + lr * 136 + nw0 + lq;

    #pragma unroll
    for (int s = 0; s < 8; s++) {
        uint32_t ah0 = sm[aoff],            ah1 = sm[aoff + 8*68];
        uint32_t ah2 = sm[aoff + 4],        ah3 = sm[aoff + 8*68 + 4];
        #pragma unroll
        for (int nt = 0; nt < 8; nt++) {
            uint32_t b0 = sm[boff + nt*8];
            uint32_t b1 = sm[boff + nt*8 + 4*136];
            mma_tf32(O.d[nt], ah0, ah1, ah2, ah3, b0, b1);
        }
        aoff += 8;
        boff += 8*136;
    }
}

__device__ __forceinline__ void gemm_fill(uint32_t* sm,
                                          const float* __restrict__ wsrc,
                                          const float* __restrict__ dsrc,
                                          int tid)
{
    #pragma unroll
    for (int t = tid * 4; t < 4096; t += 1024) {
        int o = t >> 6, c = t & 63;
        float4 v = *(const float4*)(wsrc + o * 64 + c);
        uint32_t* ah = sm + AHI_OFF + o * 68 + c;
        ah[0] = tf32u(v.x); ah[1] = tf32u(v.y);
        ah[2] = tf32u(v.z); ah[3] = tf32u(v.w);
    }
    #pragma unroll
    for (int t = tid * 4; t < 8192; t += 1024) {
        int c = t >> 7, n = t & 127;
        float4 v = *(const float4*)(dsrc + (size_t)c * HW_ + n);
        uint32_t* xs = sm + XS_OFF + c * 136 + n;
        xs[0] = tf32u(v.x); xs[1] = tf32u(v.y);
        xs[2] = tf32u(v.z); xs[3] = tf32u(v.w);
    }
}

__global__ __launch_bounds__(256, 4) void qkv_mma(const float* __restrict__ x,
                                                  const float* __restrict__ w,
                                                  const float* __restrict__ qb)
{
    extern __shared__ uint32_t smu[];
    const int tid = threadIdx.x;
    const int wid = tid >> 5, lane = tid & 31;
    const int b = blockIdx.z, ot = blockIdx.y, n0 = blockIdx.x * 128;

    gemm_fill(smu, w + (size_t)ot * 4096, x + (size_t)b * C_ * HW_ + n0, tid);
    __syncthreads();

    MmaOut O = {};
    gemm_mma_core(smu, wid, lane, O);

    const int m0  = (wid & 3) * 16;
    const int nw0 = (wid >> 2) * 64;
    const int lq  = lane >> 2, lr = lane & 3;
    const int o0  = m0 + lq;
    const float bias0 = __ldg(qb + ot*64 + o0);
    const float bias1 = __ldg(qb + ot*64 + o0 + 8);

    if (ot == 1) {
        // k channel-major
        float* r0 = g_k + ((size_t)b * C_ + o0) * HW_ + n0 + nw0;
        float* r1 = r0 + (size_t)8 * HW_;
        #pragma unroll
        for (int nt = 0; nt < 8; nt++) {
            int nb = nt*8 + lr*2;
            *(float2*)(r0 + nb) = make_float2(O.d[nt][0] + bias0, O.d[nt][1] + bias0);
            *(float2*)(r1 + nb) = make_float2(O.d[nt][2] + bias1, O.d[nt][3] + bias1);
        }
    } else {
        float* dst = (ot == 0 ? g_q : g_v) + ((size_t)b * HW_ + n0 + nw0) * C_;
        #pragma unroll
        for (int nt = 0; nt < 8; nt++) {
            int nb = nt*8 + lr*2;
            float* p0 = dst + (size_t)nb * C_;
            p0[o0]          = O.d[nt][0] + bias0;
            p0[C_ + o0]     = O.d[nt][1] + bias0;
            p0[o0 + 8]      = O.d[nt][2] + bias1;
            p0[C_ + o0 + 8] = O.d[nt][3] + bias1;
        }
    }
}

// ---------------------------------------------------------------------------
// Kernel 2: FUSED attention + projection.
// Mainloop identical to R13/R14 (proven). Afterward, the dead qs/kst smem
// regions are reused: qs <- proj_w (tf32, stride 68), kst <- normalized ao
// [c][pos] (tf32, stride 76), then a per-warp 16(o) x 32(pos) x 64(c) tf32
// mma projection writes the FINAL output directly (proj kernel eliminated).
// ---------------------------------------------------------------------------
#define QS_   0               // qs[64][68]           -> proj_w after mainloop
#define KST_  4352            // kst[64][152]         -> ao_s[64][76] after
#define VBH_  14080           // vb hi [72 keypairs][72] bf16x2
#define VBL_  19264           // vb lo [72 keypairs][72] bf16x2
#define RS_   24448           // rs[4][361]
#define ATTN_WORDS 25892
#define ATTN_SMEM (ATTN_WORDS * 4)   // 103568 bytes (2 CTAs/SM)

__global__ __launch_bounds__(256, 2) void attn_mma(const float* __restrict__ rpb,
                                                   const float* __restrict__ pw,
                                                   const float* __restrict__ pb,
                                                   float* __restrict__ out)
{
    extern __shared__ uint32_t smu[];
    const int tid = threadIdx.x;
    const int b   = blockIdx.x >> 10;
    const int wi  = blockIdx.x & 1023;
    const int y0  = (wi >> 5) * WS_, x0 = (wi & 31) * WS_;

    // ---- fills ----
    {
        const float qsc = SCALE_ * LOG2E_;
        for (int t = tid; t < 1024; t += 256) {
            int q = t >> 4, c4 = (t & 15) << 2;
            size_t pos = (size_t)(y0 + (q >> 3)) * W_ + x0 + (q & 7);
            float4 v = *(const float4*)(g_q + ((size_t)b * HW_ + pos) * C_ + c4);
            uint32_t* d = smu + QS_ + q * 68 + c4;
            d[0] = tf32u(v.x * qsc); d[1] = tf32u(v.y * qsc);
            d[2] = tf32u(v.z * qsc); d[3] = tf32u(v.w * qsc);
        }
    }
    // kst[c][kk] from channel-major g_k (halo, zero-padded)
    {
        #pragma unroll
        for (int s = 0; s < 3; s++) {
            int id = tid + s * 256;               // < 768
            int c  = (id * 683) >> 13;            // id / 12 (exact for id<2048)
            int ky = id - 12 * c;
            int gy = y0 + ky - PAD_;
            uint32_t* d = smu + KST_ + c * 152 + ky * 12;
            float2 e0 = make_float2(0.f, 0.f), e1 = make_float2(0.f, 0.f);
            float4 m0 = make_float4(0.f,0.f,0.f,0.f), m1 = m0;
            if ((unsigned)gy < H_) {
                const float* src = g_k + ((size_t)b * C_ + c) * HW_
                                 + (size_t)gy * W_ + (x0 - 2);
                if (x0 > 0)   e0 = *(const float2*)(src);
                m0 = *(const float4*)(src + 2);
                m1 = *(const float4*)(src + 6);
                if (x0 < 248) e1 = *(const float2*)(src + 10);
            }
            d[0] = tf32u(e0.x); d[1] = tf32u(e0.y);
            d[2] = tf32u(m0.x); d[3] = tf32u(m0.y); d[4] = tf32u(m0.z); d[5] = tf32u(m0.w);
            d[6] = tf32u(m1.x); d[7] = tf32u(m1.y); d[8] = tf32u(m1.z); d[9] = tf32u(m1.w);
            d[10] = tf32u(e1.x); d[11] = tf32u(e1.y);
        }
    }
    // vb hi/lo [kp][c]: pairs (v[2kp][c], v[2kp+1][c]); hi = exact bf16
    // truncation, lo = rn-rounded remainder. 12 even -> pairs share a row.
    for (int t = tid; t < 1152; t += 256) {
        int kp = t >> 4, c4 = (t & 15) << 2;
        int k0 = kp * 2;
        int ky = (k0 * 683) >> 13;
        int kx = k0 - 12 * ky;
        int gy = y0 + ky - PAD_;
        int gx0 = x0 + kx - PAD_, gx1 = gx0 + 1;
        float4 v0 = make_float4(0.f,0.f,0.f,0.f), v1 = v0;
        if ((unsigned)gy < H_) {
            const float* base = g_v + ((size_t)b * HW_ + (size_t)gy * W_) * C_;
            if ((unsigned)gx0 < W_) v0 = *(const float4*)(base + (size_t)gx0 * C_ + c4);
            if ((unsigned)gx1 < W_) v1 = *(const float4*)(base + (size_t)gx1 * C_ + c4);
        }
        uint32_t* dh = smu + VBH_ + kp * 72 + c4;
        uint32_t* dl = smu + VBL_ + kp * 72 + c4;
        dh[0] = hi_pack(v0.x, v1.x); dh[1] = hi_pack(v0.y, v1.y);
        dh[2] = hi_pack(v0.z, v1.z); dh[3] = hi_pack(v0.w, v1.w);
        dl[0] = bf16x2(v0.x - bft(v0.x), v1.x - bft(v1.x));
        dl[1] = bf16x2(v0.y - bft(v0.y), v1.y - bft(v1.y));
        dl[2] = bf16x2(v0.z - bft(v0.z), v1.z - bft(v1.z));
        dl[3] = bf16x2(v0.w - bft(v0.w), v1.w - bft(v1.w));
    }
    // rs bias * LOG2E
    for (int t = tid; t < 361 * NH_; t += 256) {
        int idx = t >> 2, h = t & 3;
        smu[RS_ + h * 361 + idx] = __float_as_uint(__ldg(rpb + t) * LOG2E_);
    }
    __syncthreads();

    // ---- per-warp attention ----
    const int w    = tid >> 5;
    const int lane = tid & 31;
    const int h    = w >> 1;
    const int q0w  = (w & 1) * 32;
    const int lq   = lane >> 2, lr = lane & 3;

    // bias row bases (q rows fixed per lane)
    int base0[2], base1[2];
    #pragma unroll
    for (int mt = 0; mt < 2; mt++) {
        int qy = (q0w + mt * 16) >> 3;
        base0[mt] = h * 361 + (7 - qy) * 19 + (7 - lq);
        base1[mt] = h * 361 + (6 - qy) * 19 + (7 - lq);
    }

    float o[2][2][4] = {};
    float lsum[2][2] = {};

    for (int chunk = 0; chunk < 3; chunk++) {
        const int kbase = chunk * 48;

        // scores: S[2mt][6nt][4] (tf32)
        float sf[2][6][4] = {};
        #pragma unroll
        for (int ks = 0; ks < 2; ks++) {
            const int c0 = h * 16 + ks * 8;
            uint32_t a[2][4];
            #pragma unroll
            for (int mt = 0; mt < 2; mt++) {
                int ao = QS_ + (q0w + mt*16 + lq) * 68 + c0 + lr;
                a[mt][0] = smu[ao];        a[mt][1] = smu[ao + 8*68];
                a[mt][2] = smu[ao + 4];    a[mt][3] = smu[ao + 8*68 + 4];
            }
            #pragma unroll
            for (int nt = 0; nt < 6; nt++) {
                int bo = KST_ + (c0 + lr) * 152 + kbase + nt*8 + lq;
                uint32_t b0 = smu[bo], b1 = smu[bo + 4*152];
                mma_tf32(sf[0][nt], a[0][0], a[0][1], a[0][2], a[0][3], b0, b1);
                mma_tf32(sf[1][nt], a[1][0], a[1][1], a[1][2], a[1][3], b0, b1);
            }
        }

        // bias + exp (in place)
        #pragma unroll
        for (int nt = 0; nt < 6; nt++) {
            int tkk = kbase + nt*8 + lr*2;
            int T = tkk + 7 * ((tkk * 683) >> 13);
            #pragma unroll
            for (int mt = 0; mt < 2; mt++) {
                float b00 = __uint_as_float(smu[RS_ + base0[mt] + T]);
                float b01 = __uint_as_float(smu[RS_ + base0[mt] + T + 1]);
                float b10 = __uint_as_float(smu[RS_ + base1[mt] + T]);
                float b11 = __uint_as_float(smu[RS_ + base1[mt] + T + 1]);
                float p0 = ex2f(sf[mt][nt][0] + b00);
                float p1 = ex2f(sf[mt][nt][1] + b01);
                float p2 = ex2f(sf[mt][nt][2] + b10);
                float p3 = ex2f(sf[mt][nt][3] + b11);
                lsum[mt][0] += p0 + p1;
                lsum[mt][1] += p2 + p3;
                sf[mt][nt][0] = p0; sf[mt][nt][1] = p1;
                sf[mt][nt][2] = p2; sf[mt][nt][3] = p3;
            }
        }

        // PV via 3-pass bf16 m16n8k16 (hi/lo split, zero shuffles)
        #pragma unroll
        for (int j = 0; j < 3; j++) {          // k16 steps
            uint32_t ah[2][4], al[2][4];
            #pragma unroll
            for (int mt = 0; mt < 2; mt++) {
                float p00 = sf[mt][2*j  ][0], p01 = sf[mt][2*j  ][1];
                float p02 = sf[mt][2*j  ][2], p03 = sf[mt][2*j  ][3];
                float p10 = sf[mt][2*j+1][0], p11 = sf[mt][2*j+1][1];
                float p12 = sf[mt][2*j+1][2], p13 = sf[mt][2*j+1][3];
                ah[mt][0] = hi_pack(p00, p01);
                ah[mt][1] = hi_pack(p02, p03);
                ah[mt][2] = hi_pack(p10, p11);
                ah[mt][3] = hi_pack(p12, p13);
                al[mt][0] = bf16x2(p00 - bft(p00), p01 - bft(p01));
                al[mt][1] = bf16x2(p02 - bft(p02), p03 - bft(p03));
                al[mt][2] = bf16x2(p10 - bft(p10), p11 - bft(p11));
                al[mt][3] = bf16x2(p12 - bft(p12), p13 - bft(p13));
            }
            const int kp0 = (kbase >> 1) + j*8 + lr;
            #pragma unroll
            for (int nt2 = 0; nt2 < 2; nt2++) {
                int boh = VBH_ + kp0 * 72 + h*16 + nt2*8 + lq;
                int bol = VBL_ + kp0 * 72 + h*16 + nt2*8 + lq;
                uint32_t bh0 = smu[boh], bh1 = smu[boh + 4*72];
                uint32_t bl0 = smu[bol], bl1 = smu[bol + 4*72];
                #pragma unroll
                for (int mt = 0; mt < 2; mt++) {
                    mma_bf16(o[mt][nt2], ah[mt][0], ah[mt][1], ah[mt][2], ah[mt][3], bh0, bh1);
                    mma_bf16(o[mt][nt2], al[mt][0], al[mt][1], al[mt][2], al[mt][3], bh0, bh1);
                    mma_bf16(o[mt][nt2], ah[mt][0], ah[mt][1], ah[mt][2], ah[mt][3], bl0, bl1);
                }
            }
        }
    }

    // ---- fused projection ----
    __syncthreads();   // all warps done reading qs/kst

    // proj_w (tf32) into QS region [o][c] stride 68
    for (int t = tid; t < 4096; t += 256) {
        int oo = t >> 6, c = t & 63;
        smu[QS_ + oo * 68 + c] = tf32u(__ldg(pw + t));
    }

    // normalized ao (tf32) into KST region as ao_s[c][pos] stride 76
    #pragma unroll
    for (int mt = 0; mt < 2; mt++) {
        float s0 = lsum[mt][0], s1 = lsum[mt][1];
        s0 += __shfl_xor_sync(0xFFFFFFFF, s0, 1);
        s0 += __shfl_xor_sync(0xFFFFFFFF, s0, 2);
        s1 += __shfl_xor_sync(0xFFFFFFFF, s1, 1);
        s1 += __shfl_xor_sync(0xFFFFFFFF, s1, 2);
        float inv0 = 1.f / s0, inv1 = 1.f / s1;

        int p0 = q0w + mt * 16 + lq;       // local pos (row lq)
        int p1 = p0 + 8;                   // row lq+8
        #pragma unroll
        for (int nt2 = 0; nt2 < 2; nt2++) {
            int dd = h*16 + nt2*8 + lr*2;
            smu[KST_ + dd     * 76 + p0] = tf32u(o[mt][nt2][0] * inv0);
            smu[KST_ + (dd+1) * 76 + p0] = tf32u(o[mt][nt2][1] * inv0);
            smu[KST_ + dd     * 76 + p1] = tf32u(o[mt][nt2][2] * inv1);
            smu[KST_ + (dd+1) * 76 + p1] = tf32u(o[mt][nt2][3] * inv1);
        }
    }
    __syncthreads();

    // per-warp proj: 16(o) x 32(pos) x 64(c) via m16n8k8 tf32
    const int m0p = (w & 3) * 16;
    const int n0p = (w >> 2) * 32;
    float dpr[4][4] = {};
    {
        int aoffp = QS_ + (m0p + lq) * 68 + lr;
        #pragma unroll
        for (int s = 0; s < 8; s++) {
            uint32_t a0 = smu[aoffp + s*8],     a1 = smu[aoffp + s*8 + 8*68];
            uint32_t a2 = smu[aoffp + s*8 + 4], a3 = smu[aoffp + s*8 + 8*68 + 4];
            #pragma unroll
            for (int nt = 0; nt < 4; nt++) {
                int bo = KST_ + (s*8 + lr) * 76 + n0p + nt*8 + lq;
                uint32_t b0 = smu[bo], b1 = smu[bo + 4*76];
                mma_tf32(dpr[nt], a0, a1, a2, a3, b0, b1);
            }
        }
    }
    // store final output (channel-major [b][o][H][W])
    {
        int o0p = m0p + lq;
        float pb0 = __ldg(pb + o0p), pb1 = __ldg(pb + o0p + 8);
        float* ro0 = out + ((size_t)b * C_ + o0p) * HW_;
        float* ro1 = ro0 + (size_t)8 * HW_;
        #pragma unroll
        for (int nt = 0; nt < 4; nt++) {
            int p = n0p + nt*8 + lr*2;
            size_t gp = (size_t)(y0 + (p >> 3)) * W_ + x0 + (p & 7);
            *(float2*)(ro0 + gp) = make_float2(dpr[nt][0] + pb0, dpr[nt][1] + pb0);
            *(float2*)(ro1 + gp) = make_float2(dpr[nt][2] + pb1, dpr[nt][3] + pb1);
        }
    }
}

// ---------------------------------------------------------------------------
extern "C" void kernel_launch(void* const* d_in, const int* in_sizes, int n_in,
                              void* d_out, int out_size)
{
    const float* x      = (const float*)d_in[0];
    const float* qkv_w  = (const float*)d_in[1];
    const float* qkv_b  = (const float*)d_in[2];
    const float* rpb    = (const float*)d_in[3];
    const float* proj_w = (const float*)d_in[4];
    const float* proj_b = (const float*)d_in[5];
    float* out = (float*)d_out;

    cudaFuncSetAttribute(qkv_mma,  cudaFuncAttributeMaxDynamicSharedMemorySize, GEMM_SMEM);
    cudaFuncSetAttribute(attn_mma, cudaFuncAttributeMaxDynamicSharedMemorySize, ATTN_SMEM);

    qkv_mma<<<dim3(HW_/128, 3, B_), 256, GEMM_SMEM>>>(x, qkv_w, qkv_b);
    attn_mma<<<B_ * NW_, 256, ATTN_SMEM>>>(rpb, proj_w, proj_b, out);
}

// round 16
// speedup vs baseline: 1.1219x; 1.1219x over previous
#include <cuda_runtime.h>
#include <cstdint>
#include <cstddef>

// Problem constants
#define B_    4
#define C_    64
#define H_    256
#define W_    256
#define HW_   (H_*W_)          // 65536
#define WS_   8
#define OWS_  12
#define PAD_  2
#define NO_   144
#define NH_   4
#define HEAD_ 16
#define SCALE_ 0.25f
#define NW_   1024
#define LOG2E_ 1.4426950408889634f

typedef unsigned long long ull;

// ---- misc helpers ----------------------------------------------------------
__device__ __forceinline__ float ex2f(float x) {
    float r; asm("ex2.approx.f32 %0, %1;" : "=f"(r) : "f"(x)); return r;
}
__device__ __forceinline__ uint32_t tf32u(float a) {   // rna round to tf32 bits
    uint32_t u; asm("cvt.rna.tf32.f32 %0, %1;" : "=r"(u) : "f"(a));
    return u;
}
// rn-rounded bf16 pair: low half = lo, high half = hi
__device__ __forceinline__ uint32_t bf16x2(float lo, float hi) {
    uint32_t r; asm("cvt.rn.satfinite.bf16x2.f32 %0, %1, %2;"
                    : "=r"(r) : "f"(hi), "f"(lo));
    return r;
}
// truncation-pack: {hi16(b), hi16(a)} -> bf16 pair (low half = a), EXACT split
__device__ __forceinline__ uint32_t hi_pack(float a, float b) {
    uint32_t r; asm("prmt.b32 %0, %1, %2, 0x7632;"
                    : "=r"(r) : "r"(__float_as_uint(a)), "r"(__float_as_uint(b)));
    return r;
}
__device__ __forceinline__ float bft(float x) {   // truncate to bf16 value
    return __uint_as_float(__float_as_uint(x) & 0xFFFF0000u);
}

// m16n8k8 tf32 mma (sm_80+ PTX)
__device__ __forceinline__ void mma_tf32(float* d,
                                         uint32_t a0, uint32_t a1,
                                         uint32_t a2, uint32_t a3,
                                         uint32_t b0, uint32_t b1)
{
    asm volatile(
        "mma.sync.aligned.m16n8k8.row.col.f32.tf32.tf32.f32 "
        "{%0,%1,%2,%3}, {%4,%5,%6,%7}, {%8,%9}, {%0,%1,%2,%3};"
        : "+f"(d[0]), "+f"(d[1]), "+f"(d[2]), "+f"(d[3])
        : "r"(a0), "r"(a1), "r"(a2), "r"(a3), "r"(b0), "r"(b1));
}

// m16n8k16 bf16 mma (sm_80+ PTX)
__device__ __forceinline__ void mma_bf16(float* d,
                                         uint32_t a0, uint32_t a1,
                                         uint32_t a2, uint32_t a3,
                                         uint32_t b0, uint32_t b1)
{
    asm volatile(
        "mma.sync.aligned.m16n8k16.row.col.f32.bf16.bf16.f32 "
        "{%0,%1,%2,%3}, {%4,%5,%6,%7}, {%8,%9}, {%0,%1,%2,%3};"
        : "+f"(d[0]), "+f"(d[1]), "+f"(d[2]), "+f"(d[3])
        : "r"(a0), "r"(a1), "r"(a2), "r"(a3), "r"(b0), "r"(b1));
}

// Scratch. q/v position-major [b][pos][c]; k and ao CHANNEL-major [b][c][pos].
__device__ float g_q [(size_t)B_*HW_*C_];
__device__ float g_k [(size_t)B_*HW_*C_];
__device__ float g_v [(size_t)B_*HW_*C_];
__device__ float g_ao[(size_t)B_*HW_*C_];

// ---------------------------------------------------------------------------
// GEMM via mma.sync tf32, SINGLE pass (weights rna-rounded; 52KB smem ->
// 4 CTAs/SM for fill-latency hiding).  D[o,n] = sum_c A[o,c]*Bm[c,n] (+bias)
// Block 64x128x64, 256 thr, warps 4(M) x 2(N).
// ---------------------------------------------------------------------------
#define AHI_OFF  0
#define XS_OFF   (64*68)
#define GEMM_SMEM ((64*68 + 64*136) * 4)   // 52224 bytes

struct MmaOut { float d[8][4]; };

__device__ __forceinline__ void gemm_mma_core(const uint32_t* sm,
                                              int wid, int lane, MmaOut& O)
{
    const int m0  = (wid & 3) * 16;
    const int nw0 = (wid >> 2) * 64;
    const int lq  = lane >> 2;
    const int lr  = lane & 3;

    int aoff = AHI_OFF + (m0 + lq) * 68 + lr;
    int boff = XS_OFF + lr * 136 + nw0 + lq;

    #pragma unroll
    for (int s = 0; s < 8; s++) {
        uint32_t ah0 = sm[aoff],            ah1 = sm[aoff + 8*68];
        uint32_t ah2 = sm[aoff + 4],        ah3 = sm[aoff + 8*68 + 4];
        #pragma unroll
        for (int nt = 0; nt < 8; nt++) {
            uint32_t b0 = sm[boff + nt*8];
            uint32_t b1 = sm[boff + nt*8 + 4*136];
            mma_tf32(O.d[nt], ah0, ah1, ah2, ah3, b0, b1);
        }
        aoff += 8;
        boff += 8*136;
    }
}

__device__ __forceinline__ void gemm_fill(uint32_t* sm,
                                          const float* __restrict__ wsrc,
                                          const float* __restrict__ dsrc,
                                          int tid)
{
    #pragma unroll
    for (int t = tid * 4; t < 4096; t += 1024) {
        int o = t >> 6, c = t & 63;
        float4 v = *(const float4*)(wsrc + o * 64 + c);
        uint32_t* ah = sm + AHI_OFF + o * 68 + c;
        ah[0] = tf32u(v.x); ah[1] = tf32u(v.y);
        ah[2] = tf32u(v.z); ah[3] = tf32u(v.w);
    }
    #pragma unroll
    for (int t = tid * 4; t < 8192; t += 1024) {
        int c = t >> 7, n = t & 127;
        float4 v = *(const float4*)(dsrc + (size_t)c * HW_ + n);
        uint32_t* xs = sm + XS_OFF + c * 136 + n;
        xs[0] = tf32u(v.x); xs[1] = tf32u(v.y);
        xs[2] = tf32u(v.z); xs[3] = tf32u(v.w);
    }
}

// ---------------------------------------------------------------------------
// Kernel 1: QKV GEMM. q/v position-major [n][c]; k CHANNEL-major [c][n].
// GRID ORDER: ot is the FASTEST dimension so the 3 consumers (q/k/v) of the
// same X tile run in adjacent blocks -> 2nd/3rd x reads hit L2, DRAM x
// traffic drops 3x.  grid (3, HW/128, B).
// ---------------------------------------------------------------------------
__global__ __launch_bounds__(256, 4) void qkv_mma(const float* __restrict__ x,
                                                  const float* __restrict__ w,
                                                  const float* __restrict__ qb)
{
    extern __shared__ uint32_t smu[];
    const int tid = threadIdx.x;
    const int wid = tid >> 5, lane = tid & 31;
    const int ot = blockIdx.x, b = blockIdx.z, n0 = blockIdx.y * 128;

    gemm_fill(smu, w + (size_t)ot * 4096, x + (size_t)b * C_ * HW_ + n0, tid);
    __syncthreads();

    MmaOut O = {};
    gemm_mma_core(smu, wid, lane, O);

    const int m0  = (wid & 3) * 16;
    const int nw0 = (wid >> 2) * 64;
    const int lq  = lane >> 2, lr = lane & 3;
    const int o0  = m0 + lq;
    const float bias0 = __ldg(qb + ot*64 + o0);
    const float bias1 = __ldg(qb + ot*64 + o0 + 8);

    if (ot == 1) {
        // k channel-major
        float* r0 = g_k + ((size_t)b * C_ + o0) * HW_ + n0 + nw0;
        float* r1 = r0 + (size_t)8 * HW_;
        #pragma unroll
        for (int nt = 0; nt < 8; nt++) {
            int nb = nt*8 + lr*2;
            *(float2*)(r0 + nb) = make_float2(O.d[nt][0] + bias0, O.d[nt][1] + bias0);
            *(float2*)(r1 + nb) = make_float2(O.d[nt][2] + bias1, O.d[nt][3] + bias1);
        }
    } else {
        float* dst = (ot == 0 ? g_q : g_v) + ((size_t)b * HW_ + n0 + nw0) * C_;
        #pragma unroll
        for (int nt = 0; nt < 8; nt++) {
            int nb = nt*8 + lr*2;
            float* p0 = dst + (size_t)nb * C_;
            p0[o0]          = O.d[nt][0] + bias0;
            p0[C_ + o0]     = O.d[nt][1] + bias0;
            p0[o0 + 8]      = O.d[nt][2] + bias1;
            p0[C_ + o0 + 8] = O.d[nt][3] + bias1;
        }
    }
}

// ---------------------------------------------------------------------------
// Kernel 2: tensor-core windowed overlap cross-attention (R13/R14, proven).
// S via tf32 mma; exp via ex2; PV via 3-pass bf16 hi/lo, zero shuffles.
// ---------------------------------------------------------------------------
#define QS_   0               // qs[64][68]
#define KST_  4352            // kst[64][152]
#define VBH_  14080           // vb hi [72 keypairs][72] bf16x2
#define VBL_  19264           // vb lo [72 keypairs][72] bf16x2
#define RS_   24448           // rs[4][361]
#define ATTN_WORDS 25892
#define ATTN_SMEM (ATTN_WORDS * 4)   // 103568 bytes (2 CTAs/SM)

__global__ __launch_bounds__(256, 2) void attn_mma(const float* __restrict__ rpb)
{
    extern __shared__ uint32_t smu[];
    const int tid = threadIdx.x;
    const int b   = blockIdx.x >> 10;
    const int wi  = blockIdx.x & 1023;
    const int y0  = (wi >> 5) * WS_, x0 = (wi & 31) * WS_;

    // ---- fills ----
    {
        const float qsc = SCALE_ * LOG2E_;
        for (int t = tid; t < 1024; t += 256) {
            int q = t >> 4, c4 = (t & 15) << 2;
            size_t pos = (size_t)(y0 + (q >> 3)) * W_ + x0 + (q & 7);
            float4 v = *(const float4*)(g_q + ((size_t)b * HW_ + pos) * C_ + c4);
            uint32_t* d = smu + QS_ + q * 68 + c4;
            d[0] = tf32u(v.x * qsc); d[1] = tf32u(v.y * qsc);
            d[2] = tf32u(v.z * qsc); d[3] = tf32u(v.w * qsc);
        }
    }
    // kst[c][kk] from channel-major g_k (halo, zero-padded)
    {
        #pragma unroll
        for (int s = 0; s < 3; s++) {
            int id = tid + s * 256;               // < 768
            int c  = (id * 683) >> 13;            // id / 12 (exact for id<2048)
            int ky = id - 12 * c;
            int gy = y0 + ky - PAD_;
            uint32_t* d = smu + KST_ + c * 152 + ky * 12;
            float2 e0 = make_float2(0.f, 0.f), e1 = make_float2(0.f, 0.f);
            float4 m0 = make_float4(0.f,0.f,0.f,0.f), m1 = m0;
            if ((unsigned)gy < H_) {
                const float* src = g_k + ((size_t)b * C_ + c) * HW_
                                 + (size_t)gy * W_ + (x0 - 2);
                if (x0 > 0)   e0 = *(const float2*)(src);
                m0 = *(const float4*)(src + 2);
                m1 = *(const float4*)(src + 6);
                if (x0 < 248) e1 = *(const float2*)(src + 10);
            }
            d[0] = tf32u(e0.x); d[1] = tf32u(e0.y);
            d[2] = tf32u(m0.x); d[3] = tf32u(m0.y); d[4] = tf32u(m0.z); d[5] = tf32u(m0.w);
            d[6] = tf32u(m1.x); d[7] = tf32u(m1.y); d[8] = tf32u(m1.z); d[9] = tf32u(m1.w);
            d[10] = tf32u(e1.x); d[11] = tf32u(e1.y);
        }
    }
    // vb hi/lo [kp][c]: pairs (v[2kp][c], v[2kp+1][c]); hi = exact bf16
    // truncation, lo = rn-rounded remainder. 12 even -> pairs share a row.
    for (int t = tid; t < 1152; t += 256) {
        int kp = t >> 4, c4 = (t & 15) << 2;
        int k0 = kp * 2;
        int ky = (k0 * 683) >> 13;
        int kx = k0 - 12 * ky;
        int gy = y0 + ky - PAD_;
        int gx0 = x0 + kx - PAD_, gx1 = gx0 + 1;
        float4 v0 = make_float4(0.f,0.f,0.f,0.f), v1 = v0;
        if ((unsigned)gy < H_) {
            const float* base = g_v + ((size_t)b * HW_ + (size_t)gy * W_) * C_;
            if ((unsigned)gx0 < W_) v0 = *(const float4*)(base + (size_t)gx0 * C_ + c4);
            if ((unsigned)gx1 < W_) v1 = *(const float4*)(base + (size_t)gx1 * C_ + c4);
        }
        uint32_t* dh = smu + VBH_ + kp * 72 + c4;
        uint32_t* dl = smu + VBL_ + kp * 72 + c4;
        dh[0] = hi_pack(v0.x, v1.x); dh[1] = hi_pack(v0.y, v1.y);
        dh[2] = hi_pack(v0.z, v1.z); dh[3] = hi_pack(v0.w, v1.w);
        dl[0] = bf16x2(v0.x - bft(v0.x), v1.x - bft(v1.x));
        dl[1] = bf16x2(v0.y - bft(v0.y), v1.y - bft(v1.y));
        dl[2] = bf16x2(v0.z - bft(v0.z), v1.z - bft(v1.z));
        dl[3] = bf16x2(v0.w - bft(v0.w), v1.w - bft(v1.w));
    }
    // rs bias * LOG2E
    for (int t = tid; t < 361 * NH_; t += 256) {
        int idx = t >> 2, h = t & 3;
        smu[RS_ + h * 361 + idx] = __float_as_uint(__ldg(rpb + t) * LOG2E_);
    }
    __syncthreads();

    // ---- per-warp attention ----
    const int w    = tid >> 5;
    const int lane = tid & 31;
    const int h    = w >> 1;
    const int q0w  = (w & 1) * 32;
    const int lq   = lane >> 2, lr = lane & 3;

    // bias row bases (q rows fixed per lane)
    int base0[2], base1[2];
    #pragma unroll
    for (int mt = 0; mt < 2; mt++) {
        int qy = (q0w + mt * 16) >> 3;
        base0[mt] = h * 361 + (7 - qy) * 19 + (7 - lq);
        base1[mt] = h * 361 + (6 - qy) * 19 + (7 - lq);
    }

    float o[2][2][4] = {};
    float lsum[2][2] = {};

    for (int chunk = 0; chunk < 3; chunk++) {
        const int kbase = chunk * 48;

        // scores: S[2mt][6nt][4] (tf32)
        float sf[2][6][4] = {};
        #pragma unroll
        for (int ks = 0; ks < 2; ks++) {
            const int c0 = h * 16 + ks * 8;
            uint32_t a[2][4];
            #pragma unroll
            for (int mt = 0; mt < 2; mt++) {
                int ao = QS_ + (q0w + mt*16 + lq) * 68 + c0 + lr;
                a[mt][0] = smu[ao];        a[mt][1] = smu[ao + 8*68];
                a[mt][2] = smu[ao + 4];    a[mt][3] = smu[ao + 8*68 + 4];
            }
            #pragma unroll
            for (int nt = 0; nt < 6; nt++) {
                int bo = KST_ + (c0 + lr) * 152 + kbase + nt*8 + lq;
                uint32_t b0 = smu[bo], b1 = smu[bo + 4*152];
                mma_tf32(sf[0][nt], a[0][0], a[0][1], a[0][2], a[0][3], b0, b1);
                mma_tf32(sf[1][nt], a[1][0], a[1][1], a[1][2], a[1][3], b0, b1);
            }
        }

        // bias + exp (in place)
        #pragma unroll
        for (int nt = 0; nt < 6; nt++) {
            int tkk = kbase + nt*8 + lr*2;
            int T = tkk + 7 * ((tkk * 683) >> 13);
            #pragma unroll
            for (int mt = 0; mt < 2; mt++) {
                float b00 = __uint_as_float(smu[RS_ + base0[mt] + T]);
                float b01 = __uint_as_float(smu[RS_ + base0[mt] + T + 1]);
                float b10 = __uint_as_float(smu[RS_ + base1[mt] + T]);
                float b11 = __uint_as_float(smu[RS_ + base1[mt] + T + 1]);
                float p0 = ex2f(sf[mt][nt][0] + b00);
                float p1 = ex2f(sf[mt][nt][1] + b01);
                float p2 = ex2f(sf[mt][nt][2] + b10);
                float p3 = ex2f(sf[mt][nt][3] + b11);
                lsum[mt][0] += p0 + p1;
                lsum[mt][1] += p2 + p3;
                sf[mt][nt][0] = p0; sf[mt][nt][1] = p1;
                sf[mt][nt][2] = p2; sf[mt][nt][3] = p3;
            }
        }

        // PV via 3-pass bf16 m16n8k16 (hi/lo split, zero shuffles)
        #pragma unroll
        for (int j = 0; j < 3; j++) {          // k16 steps
            uint32_t ah[2][4], al[2][4];
            #pragma unroll
            for (int mt = 0; mt < 2; mt++) {
                float p00 = sf[mt][2*j  ][0], p01 = sf[mt][2*j  ][1];
                float p02 = sf[mt][2*j  ][2], p03 = sf[mt][2*j  ][3];
                float p10 = sf[mt][2*j+1][0], p11 = sf[mt][2*j+1][1];
                float p12 = sf[mt][2*j+1][2], p13 = sf[mt][2*j+1][3];
                ah[mt][0] = hi_pack(p00, p01);
                ah[mt][1] = hi_pack(p02, p03);
                ah[mt][2] = hi_pack(p10, p11);
                ah[mt][3] = hi_pack(p12, p13);
                al[mt][0] = bf16x2(p00 - bft(p00), p01 - bft(p01));
                al[mt][1] = bf16x2(p02 - bft(p02), p03 - bft(p03));
                al[mt][2] = bf16x2(p10 - bft(p10), p11 - bft(p11));
                al[mt][3] = bf16x2(p12 - bft(p12), p13 - bft(p13));
            }
            const int kp0 = (kbase >> 1) + j*8 + lr;
            #pragma unroll
            for (int nt2 = 0; nt2 < 2; nt2++) {
                int boh = VBH_ + kp0 * 72 + h*16 + nt2*8 + lq;
                int bol = VBL_ + kp0 * 72 + h*16 + nt2*8 + lq;
                uint32_t bh0 = smu[boh], bh1 = smu[boh + 4*72];
                uint32_t bl0 = smu[bol], bl1 = smu[bol + 4*72];
                #pragma unroll
                for (int mt = 0; mt < 2; mt++) {
                    mma_bf16(o[mt][nt2], ah[mt][0], ah[mt][1], ah[mt][2], ah[mt][3], bh0, bh1);
                    mma_bf16(o[mt][nt2], al[mt][0], al[mt][1], al[mt][2], al[mt][3], bh0, bh1);
                    mma_bf16(o[mt][nt2], ah[mt][0], ah[mt][1], ah[mt][2], ah[mt][3], bl0, bl1);
                }
            }
        }
    }

    // reduce row sums across lane quads, normalize, store channel-major
    #pragma unroll
    for (int mt = 0; mt < 2; mt++) {
        float s0 = lsum[mt][0], s1 = lsum[mt][1];
        s0 += __shfl_xor_sync(0xFFFFFFFF, s0, 1);
        s0 += __shfl_xor_sync(0xFFFFFFFF, s0, 2);
        s1 += __shfl_xor_sync(0xFFFFFFFF, s1, 1);
        s1 += __shfl_xor_sync(0xFFFFFFFF, s1, 2);
        float inv0 = 1.f / s0, inv1 = 1.f / s1;

        int qq = q0w + mt * 16;
        size_t pos = (size_t)(y0 + (qq >> 3)) * W_ + x0 + lq;
        #pragma unroll
        for (int nt2 = 0; nt2 < 2; nt2++) {
            int dd = h*16 + nt2*8 + lr*2;
            float* r0 = g_ao + ((size_t)b * C_ + dd) * HW_ + pos;
            float* r1 = r0 + HW_;           // dd+1
            r0[0]   = o[mt][nt2][0] * inv0;
            r1[0]   = o[mt][nt2][1] * inv0;
            r0[W_]  = o[mt][nt2][2] * inv1; // row q+8 => pos+256
            r1[W_]  = o[mt][nt2][3] * inv1;
        }
    }
}

// ---------------------------------------------------------------------------
// Kernel 3: projection GEMM (single-pass tf32, R14 proven). B = g_ao
// channel-major. Output channel-major.
// ---------------------------------------------------------------------------
__global__ __launch_bounds__(256, 4) void proj_mma(const float* __restrict__ w,
                                                   const float* __restrict__ pb,
                                                   float* __restrict__ out)
{
    extern __shared__ uint32_t smu[];
    const int tid = threadIdx.x;
    const int wid = tid >> 5, lane = tid & 31;
    const int b = blockIdx.y, n0 = blockIdx.x * 128;

    gemm_fill(smu, w, g_ao + (size_t)b * C_ * HW_ + n0, tid);
    __syncthreads();

    MmaOut O = {};
    gemm_mma_core(smu, wid, lane, O);

    const int m0  = (wid & 3) * 16;
    const int nw0 = (wid >> 2) * 64;
    const int lq  = lane >> 2, lr = lane & 3;
    const int o0  = m0 + lq;
    const float bias0 = __ldg(pb + o0);
    const float bias1 = __ldg(pb + o0 + 8);

    float* r0 = out + ((size_t)b * C_ + o0) * HW_ + n0 + nw0;
    float* r1 = out + ((size_t)b * C_ + o0 + 8) * HW_ + n0 + nw0;
    #pragma unroll
    for (int nt = 0; nt < 8; nt++) {
        int nb = nt*8 + lr*2;
        *(float2*)(r0 + nb) = make_float2(O.d[nt][0] + bias0, O.d[nt][1] + bias0);
        *(float2*)(r1 + nb) = make_float2(O.d[nt][2] + bias1, O.d[nt][3] + bias1);
    }
}

// ---------------------------------------------------------------------------
extern "C" void kernel_launch(void* const* d_in, const int* in_sizes, int n_in,
                              void* d_out, int out_size)
{
    const float* x      = (const float*)d_in[0];
    const float* qkv_w  = (const float*)d_in[1];
    const float* qkv_b  = (const float*)d_in[2];
    const float* rpb    = (const float*)d_in[3];
    const float* proj_w = (const float*)d_in[4];
    const float* proj_b = (const float*)d_in[5];
    float* out = (float*)d_out;

    cudaFuncSetAttribute(qkv_mma,  cudaFuncAttributeMaxDynamicSharedMemorySize, GEMM_SMEM);
    cudaFuncSetAttribute(proj_mma, cudaFuncAttributeMaxDynamicSharedMemorySize, GEMM_SMEM);
    cudaFuncSetAttribute(attn_mma, cudaFuncAttributeMaxDynamicSharedMemorySize, ATTN_SMEM);

    qkv_mma<<<dim3(3, HW_/128, B_), 256, GEMM_SMEM>>>(x, qkv_w, qkv_b);
    attn_mma<<<B_ * NW_, 256, ATTN_SMEM>>>(rpb);
    proj_mma<<<dim3(HW_/128, B_), 256, GEMM_SMEM>>>(proj_w, proj_b, out);
}

// round 17
// speedup vs baseline: 1.2451x; 1.1098x over previous
#include <cuda_runtime.h>
#include <cstdint>
#include <cstddef>

// Problem constants
#define B_    4
#define C_    64
#define H_    256
#define W_    256
#define HW_   (H_*W_)          // 65536
#define WS_   8
#define OWS_  12
#define PAD_  2
#define NO_   144
#define NH_   4
#define HEAD_ 16
#define SCALE_ 0.25f
#define NW_   1024
#define LOG2E_ 1.4426950408889634f

typedef unsigned long long ull;

// ---- misc helpers ----------------------------------------------------------
__device__ __forceinline__ float ex2f(float x) {
    float r; asm("ex2.approx.f32 %0, %1;" : "=f"(r) : "f"(x)); return r;
}
__device__ __forceinline__ uint32_t tf32u(float a) {   // rna round to tf32 bits
    uint32_t u; asm("cvt.rna.tf32.f32 %0, %1;" : "=r"(u) : "f"(a));
    return u;
}
// rn-rounded f16 pair: low half = lo, high half = hi
__device__ __forceinline__ uint32_t f16x2(float lo, float hi) {
    uint32_t r; asm("cvt.rn.f16x2.f32 %0, %1, %2;"
                    : "=r"(r) : "f"(hi), "f"(lo));
    return r;
}

// m16n8k8 tf32 mma (sm_80+ PTX)
__device__ __forceinline__ void mma_tf32(float* d,
                                         uint32_t a0, uint32_t a1,
                                         uint32_t a2, uint32_t a3,
                                         uint32_t b0, uint32_t b1)
{
    asm volatile(
        "mma.sync.aligned.m16n8k8.row.col.f32.tf32.tf32.f32 "
        "{%0,%1,%2,%3}, {%4,%5,%6,%7}, {%8,%9}, {%0,%1,%2,%3};"
        : "+f"(d[0]), "+f"(d[1]), "+f"(d[2]), "+f"(d[3])
        : "r"(a0), "r"(a1), "r"(a2), "r"(a3), "r"(b0), "r"(b1));
}

// m16n8k16 fp16 mma, f32 accum (sm_80+ PTX)
__device__ __forceinline__ void mma_f16(float* d,
                                        uint32_t a0, uint32_t a1,
                                        uint32_t a2, uint32_t a3,
                                        uint32_t b0, uint32_t b1)
{
    asm volatile(
        "mma.sync.aligned.m16n8k16.row.col.f32.f16.f16.f32 "
        "{%0,%1,%2,%3}, {%4,%5,%6,%7}, {%8,%9}, {%0,%1,%2,%3};"
        : "+f"(d[0]), "+f"(d[1]), "+f"(d[2]), "+f"(d[3])
        : "r"(a0), "r"(a1), "r"(a2), "r"(a3), "r"(b0), "r"(b1));
}

// Scratch. q/v position-major [b][pos][c]; k and ao CHANNEL-major [b][c][pos].
__device__ float g_q [(size_t)B_*HW_*C_];
__device__ float g_k [(size_t)B_*HW_*C_];
__device__ float g_v [(size_t)B_*HW_*C_];
__device__ float g_ao[(size_t)B_*HW_*C_];

// ---------------------------------------------------------------------------
// GEMM via mma.sync tf32, single pass (R14/R16, proven).
// Block 64x128x64, 256 thr, warps 4(M) x 2(N), 4 CTAs/SM.
// ---------------------------------------------------------------------------
#define AHI_OFF  0
#define XS_OFF   (64*68)
#define GEMM_SMEM ((64*68 + 64*136) * 4)   // 52224 bytes

struct MmaOut { float d[8][4]; };

__device__ __forceinline__ void gemm_mma_core(const uint32_t* sm,
                                              int wid, int lane, MmaOut& O)
{
    const int m0  = (wid & 3) * 16;
    const int nw0 = (wid >> 2) * 64;
    const int lq  = lane >> 2;
    const int lr  = lane & 3;

    int aoff = AHI_OFF + (m0 + lq) * 68 + lr;
    int boff = XS_OFF + lr * 136 + nw0 + lq;

    #pragma unroll
    for (int s = 0; s < 8; s++) {
        uint32_t ah0 = sm[aoff],            ah1 = sm[aoff + 8*68];
        uint32_t ah2 = sm[aoff + 4],        ah3 = sm[aoff + 8*68 + 4];
        #pragma unroll
        for (int nt = 0; nt < 8; nt++) {
            uint32_t b0 = sm[boff + nt*8];
            uint32_t b1 = sm[boff + nt*8 + 4*136];
            mma_tf32(O.d[nt], ah0, ah1, ah2, ah3, b0, b1);
        }
        aoff += 8;
        boff += 8*136;
    }
}

__device__ __forceinline__ void gemm_fill(uint32_t* sm,
                                          const float* __restrict__ wsrc,
                                          const float* __restrict__ dsrc,
                                          int tid)
{
    #pragma unroll
    for (int t = tid * 4; t < 4096; t += 1024) {
        int o = t >> 6, c = t & 63;
        float4 v = *(const float4*)(wsrc + o * 64 + c);
        uint32_t* ah = sm + AHI_OFF + o * 68 + c;
        ah[0] = tf32u(v.x); ah[1] = tf32u(v.y);
        ah[2] = tf32u(v.z); ah[3] = tf32u(v.w);
    }
    #pragma unroll
    for (int t = tid * 4; t < 8192; t += 1024) {
        int c = t >> 7, n = t & 127;
        float4 v = *(const float4*)(dsrc + (size_t)c * HW_ + n);
        uint32_t* xs = sm + XS_OFF + c * 136 + n;
        xs[0] = tf32u(v.x); xs[1] = tf32u(v.y);
        xs[2] = tf32u(v.z); xs[3] = tf32u(v.w);
    }
}

// ---------------------------------------------------------------------------
// Kernel 1: QKV GEMM. q/v position-major [n][c]; k CHANNEL-major [c][n].
// grid (3, HW/128, B) — ot fastest (R16).
// ---------------------------------------------------------------------------
__global__ __launch_bounds__(256, 4) void qkv_mma(const float* __restrict__ x,
                                                  const float* __restrict__ w,
                                                  const float* __restrict__ qb)
{
    extern __shared__ uint32_t smu[];
    const int tid = threadIdx.x;
    const int wid = tid >> 5, lane = tid & 31;
    const int ot = blockIdx.x, b = blockIdx.z, n0 = blockIdx.y * 128;

    gemm_fill(smu, w + (size_t)ot * 4096, x + (size_t)b * C_ * HW_ + n0, tid);
    __syncthreads();

    MmaOut O = {};
    gemm_mma_core(smu, wid, lane, O);

    const int m0  = (wid & 3) * 16;
    const int nw0 = (wid >> 2) * 64;
    const int lq  = lane >> 2, lr = lane & 3;
    const int o0  = m0 + lq;
    const float bias0 = __ldg(qb + ot*64 + o0);
    const float bias1 = __ldg(qb + ot*64 + o0 + 8);

    if (ot == 1) {
        // k channel-major
        float* r0 = g_k + ((size_t)b * C_ + o0) * HW_ + n0 + nw0;
        float* r1 = r0 + (size_t)8 * HW_;
        #pragma unroll
        for (int nt = 0; nt < 8; nt++) {
            int nb = nt*8 + lr*2;
            *(float2*)(r0 + nb) = make_float2(O.d[nt][0] + bias0, O.d[nt][1] + bias0);
            *(float2*)(r1 + nb) = make_float2(O.d[nt][2] + bias1, O.d[nt][3] + bias1);
        }
    } else {
        float* dst = (ot == 0 ? g_q : g_v) + ((size_t)b * HW_ + n0 + nw0) * C_;
        #pragma unroll
        for (int nt = 0; nt < 8; nt++) {
            int nb = nt*8 + lr*2;
            float* p0 = dst + (size_t)nb * C_;
            p0[o0]          = O.d[nt][0] + bias0;
            p0[C_ + o0]     = O.d[nt][1] + bias0;
            p0[o0 + 8]      = O.d[nt][2] + bias1;
            p0[C_ + o0 + 8] = O.d[nt][3] + bias1;
        }
    }
}

// ---------------------------------------------------------------------------
// Kernel 2: tensor-core windowed overlap cross-attention.
// S via tf32 mma; exp via ex2; PV via SINGLE-PASS fp16 m16n8k16
// (11-bit mantissa: rel err ~3e-4 vs bf16's 2.4e-3; zero-shuffle
// accumulator->A-frag identity unchanged). V stored as f16x2 key-pairs.
// ---------------------------------------------------------------------------
#define QS_   0               // qs[64][68]
#define KST_  4352            // kst[64][152]
#define VH_   14080           // v  [72 keypairs][72] f16x2
#define RS_   19264           // rs[4][361]
#define ATTN_WORDS 20708
#define ATTN_SMEM (ATTN_WORDS * 4)   // 82832 bytes (2 CTAs/SM)

__global__ __launch_bounds__(256, 2) void attn_mma(const float* __restrict__ rpb)
{
    extern __shared__ uint32_t smu[];
    const int tid = threadIdx.x;
    const int b   = blockIdx.x >> 10;
    const int wi  = blockIdx.x & 1023;
    const int y0  = (wi >> 5) * WS_, x0 = (wi & 31) * WS_;

    // ---- fills ----
    {
        const float qsc = SCALE_ * LOG2E_;
        for (int t = tid; t < 1024; t += 256) {
            int q = t >> 4, c4 = (t & 15) << 2;
            size_t pos = (size_t)(y0 + (q >> 3)) * W_ + x0 + (q & 7);
            float4 v = *(const float4*)(g_q + ((size_t)b * HW_ + pos) * C_ + c4);
            uint32_t* d = smu + QS_ + q * 68 + c4;
            d[0] = tf32u(v.x * qsc); d[1] = tf32u(v.y * qsc);
            d[2] = tf32u(v.z * qsc); d[3] = tf32u(v.w * qsc);
        }
    }
    // kst[c][kk] from channel-major g_k (halo, zero-padded)
    {
        #pragma unroll
        for (int s = 0; s < 3; s++) {
            int id = tid + s * 256;               // < 768
            int c  = (id * 683) >> 13;            // id / 12 (exact for id<2048)
            int ky = id - 12 * c;
            int gy = y0 + ky - PAD_;
            uint32_t* d = smu + KST_ + c * 152 + ky * 12;
            float2 e0 = make_float2(0.f, 0.f), e1 = make_float2(0.f, 0.f);
            float4 m0 = make_float4(0.f,0.f,0.f,0.f), m1 = m0;
            if ((unsigned)gy < H_) {
                const float* src = g_k + ((size_t)b * C_ + c) * HW_
                                 + (size_t)gy * W_ + (x0 - 2);
                if (x0 > 0)   e0 = *(const float2*)(src);
                m0 = *(const float4*)(src + 2);
                m1 = *(const float4*)(src + 6);
                if (x0 < 248) e1 = *(const float2*)(src + 10);
            }
            d[0] = tf32u(e0.x); d[1] = tf32u(e0.y);
            d[2] = tf32u(m0.x); d[3] = tf32u(m0.y); d[4] = tf32u(m0.z); d[5] = tf32u(m0.w);
            d[6] = tf32u(m1.x); d[7] = tf32u(m1.y); d[8] = tf32u(m1.z); d[9] = tf32u(m1.w);
            d[10] = tf32u(e1.x); d[11] = tf32u(e1.y);
        }
    }
    // vh[kp][c]: f16x2 of (v[2kp][c], v[2kp+1][c]); pairs share a row.
    for (int t = tid; t < 1152; t += 256) {
        int kp = t >> 4, c4 = (t & 15) << 2;
        int k0 = kp * 2;
        int ky = (k0 * 683) >> 13;
        int kx = k0 - 12 * ky;
        int gy = y0 + ky - PAD_;
        int gx0 = x0 + kx - PAD_, gx1 = gx0 + 1;
        float4 v0 = make_float4(0.f,0.f,0.f,0.f), v1 = v0;
        if ((unsigned)gy < H_) {
            const float* base = g_v + ((size_t)b * HW_ + (size_t)gy * W_) * C_;
            if ((unsigned)gx0 < W_) v0 = *(const float4*)(base + (size_t)gx0 * C_ + c4);
            if ((unsigned)gx1 < W_) v1 = *(const float4*)(base + (size_t)gx1 * C_ + c4);
        }
        uint32_t* dh = smu + VH_ + kp * 72 + c4;
        dh[0] = f16x2(v0.x, v1.x); dh[1] = f16x2(v0.y, v1.y);
        dh[2] = f16x2(v0.z, v1.z); dh[3] = f16x2(v0.w, v1.w);
    }
    // rs bias * LOG2E
    for (int t = tid; t < 361 * NH_; t += 256) {
        int idx = t >> 2, h = t & 3;
        smu[RS_ + h * 361 + idx] = __float_as_uint(__ldg(rpb + t) * LOG2E_);
    }
    __syncthreads();

    // ---- per-warp attention ----
    const int w    = tid >> 5;
    const int lane = tid & 31;
    const int h    = w >> 1;
    const int q0w  = (w & 1) * 32;
    const int lq   = lane >> 2, lr = lane & 3;

    // bias row bases (q rows fixed per lane)
    int base0[2], base1[2];
    #pragma unroll
    for (int mt = 0; mt < 2; mt++) {
        int qy = (q0w + mt * 16) >> 3;
        base0[mt] = h * 361 + (7 - qy) * 19 + (7 - lq);
        base1[mt] = h * 361 + (6 - qy) * 19 + (7 - lq);
    }

    float o[2][2][4] = {};
    float lsum[2][2] = {};

    for (int chunk = 0; chunk < 3; chunk++) {
        const int kbase = chunk * 48;

        // scores: S[2mt][6nt][4] (tf32)
        float sf[2][6][4] = {};
        #pragma unroll
        for (int ks = 0; ks < 2; ks++) {
            const int c0 = h * 16 + ks * 8;
            uint32_t a[2][4];
            #pragma unroll
            for (int mt = 0; mt < 2; mt++) {
                int ao = QS_ + (q0w + mt*16 + lq) * 68 + c0 + lr;
                a[mt][0] = smu[ao];        a[mt][1] = smu[ao + 8*68];
                a[mt][2] = smu[ao + 4];    a[mt][3] = smu[ao + 8*68 + 4];
            }
            #pragma unroll
            for (int nt = 0; nt < 6; nt++) {
                int bo = KST_ + (c0 + lr) * 152 + kbase + nt*8 + lq;
                uint32_t b0 = smu[bo], b1 = smu[bo + 4*152];
                mma_tf32(sf[0][nt], a[0][0], a[0][1], a[0][2], a[0][3], b0, b1);
                mma_tf32(sf[1][nt], a[1][0], a[1][1], a[1][2], a[1][3], b0, b1);
            }
        }

        // bias + exp (in place)
        #pragma unroll
        for (int nt = 0; nt < 6; nt++) {
            int tkk = kbase + nt*8 + lr*2;
            int T = tkk + 7 * ((tkk * 683) >> 13);
            #pragma unroll
            for (int mt = 0; mt < 2; mt++) {
                float b00 = __uint_as_float(smu[RS_ + base0[mt] + T]);
                float b01 = __uint_as_float(smu[RS_ + base0[mt] + T + 1]);
                float b10 = __uint_as_float(smu[RS_ + base1[mt] + T]);
                float b11 = __uint_as_float(smu[RS_ + base1[mt] + T + 1]);
                float p0 = ex2f(sf[mt][nt][0] + b00);
                float p1 = ex2f(sf[mt][nt][1] + b01);
                float p2 = ex2f(sf[mt][nt][2] + b10);
                float p3 = ex2f(sf[mt][nt][3] + b11);
                lsum[mt][0] += p0 + p1;
                lsum[mt][1] += p2 + p3;
                sf[mt][nt][0] = p0; sf[mt][nt][1] = p1;
                sf[mt][nt][2] = p2; sf[mt][nt][3] = p3;
            }
        }

        // PV via single-pass fp16 m16n8k16 (zero shuffles)
        #pragma unroll
        for (int j = 0; j < 3; j++) {          // k16 steps
            uint32_t a[2][4];
            #pragma unroll
            for (int mt = 0; mt < 2; mt++) {
                a[mt][0] = f16x2(sf[mt][2*j  ][0], sf[mt][2*j  ][1]);
                a[mt][1] = f16x2(sf[mt][2*j  ][2], sf[mt][2*j  ][3]);
                a[mt][2] = f16x2(sf[mt][2*j+1][0], sf[mt][2*j+1][1]);
                a[mt][3] = f16x2(sf[mt][2*j+1][2], sf[mt][2*j+1][3]);
            }
            const int kp0 = (kbase >> 1) + j*8 + lr;
            #pragma unroll
            for (int nt2 = 0; nt2 < 2; nt2++) {
                int bo = VH_ + kp0 * 72 + h*16 + nt2*8 + lq;
                uint32_t b0 = smu[bo], b1 = smu[bo + 4*72];
                mma_f16(o[0][nt2], a[0][0], a[0][1], a[0][2], a[0][3], b0, b1);
                mma_f16(o[1][nt2], a[1][0], a[1][1], a[1][2], a[1][3], b0, b1);
            }
        }
    }

    // reduce row sums across lane quads, normalize, store channel-major
    #pragma unroll
    for (int mt = 0; mt < 2; mt++) {
        float s0 = lsum[mt][0], s1 = lsum[mt][1];
        s0 += __shfl_xor_sync(0xFFFFFFFF, s0, 1);
        s0 += __shfl_xor_sync(0xFFFFFFFF, s0, 2);
        s1 += __shfl_xor_sync(0xFFFFFFFF, s1, 1);
        s1 += __shfl_xor_sync(0xFFFFFFFF, s1, 2);
        float inv0 = 1.f / s0, inv1 = 1.f / s1;

        int qq = q0w + mt * 16;
        size_t pos = (size_t)(y0 + (qq >> 3)) * W_ + x0 + lq;
        #pragma unroll
        for (int nt2 = 0; nt2 < 2; nt2++) {
            int dd = h*16 + nt2*8 + lr*2;
            float* r0 = g_ao + ((size_t)b * C_ + dd) * HW_ + pos;
            float* r1 = r0 + HW_;           // dd+1
            r0[0]   = o[mt][nt2][0] * inv0;
            r1[0]   = o[mt][nt2][1] * inv0;
            r0[W_]  = o[mt][nt2][2] * inv1; // row q+8 => pos+256
            r1[W_]  = o[mt][nt2][3] * inv1;
        }
    }
}

// ---------------------------------------------------------------------------
// Kernel 3: projection GEMM (single-pass tf32, R14 proven). B = g_ao
// channel-major. Output channel-major.
// ---------------------------------------------------------------------------
__global__ __launch_bounds__(256, 4) void proj_mma(const float* __restrict__ w,
                                                   const float* __restrict__ pb,
                                                   float* __restrict__ out)
{
    extern __shared__ uint32_t smu[];
    const int tid = threadIdx.x;
    const int wid = tid >> 5, lane = tid & 31;
    const int b = blockIdx.y, n0 = blockIdx.x * 128;

    gemm_fill(smu, w, g_ao + (size_t)b * C_ * HW_ + n0, tid);
    __syncthreads();

    MmaOut O = {};
    gemm_mma_core(smu, wid, lane, O);

    const int m0  = (wid & 3) * 16;
    const int nw0 = (wid >> 2) * 64;
    const int lq  = lane >> 2, lr = lane & 3;
    const int o0  = m0 + lq;
    const float bias0 = __ldg(pb + o0);
    const float bias1 = __ldg(pb + o0 + 8);

    float* r0 = out + ((size_t)b * C_ + o0) * HW_ + n0 + nw0;
    float* r1 = out + ((size_t)b * C_ + o0 + 8) * HW_ + n0 + nw0;
    #pragma unroll
    for (int nt = 0; nt < 8; nt++) {
        int nb = nt*8 + lr*2;
        *(float2*)(r0 + nb) = make_float2(O.d[nt][0] + bias0, O.d[nt][1] + bias0);
        *(float2*)(r1 + nb) = make_float2(O.d[nt][2] + bias1, O.d[nt][3] + bias1);
    }
}

// ---------------------------------------------------------------------------
extern "C" void kernel_launch(void* const* d_in, const int* in_sizes, int n_in,
                              void* d_out, int out_size)
{
    const float* x      = (const float*)d_in[0];
    const float* qkv_w  = (const float*)d_in[1];
    const float* qkv_b  = (const float*)d_in[2];
    const float* rpb    = (const float*)d_in[3];
    const float* proj_w = (const float*)d_in[4];
    const float* proj_b = (const float*)d_in[5];
    float* out = (float*)d_out;

    cudaFuncSetAttribute(qkv_mma,  cudaFuncAttributeMaxDynamicSharedMemorySize, GEMM_SMEM);
    cudaFuncSetAttribute(proj_mma, cudaFuncAttributeMaxDynamicSharedMemorySize, GEMM_SMEM);
    cudaFuncSetAttribute(attn_mma, cudaFuncAttributeMaxDynamicSharedMemorySize, ATTN_SMEM);

    qkv_mma<<<dim3(3, HW_/128, B_), 256, GEMM_SMEM>>>(x, qkv_w, qkv_b);
    attn_mma<<<B_ * NW_, 256, ATTN_SMEM>>>(rpb);
    proj_mma<<<dim3(HW_/128, B_), 256, GEMM_SMEM>>>(proj_w, proj_b, out);
}